// round 5
// baseline (speedup 1.0000x reference)
#include <cuda_runtime.h>
#include <math.h>
#include <stdint.h>

#define C 100            // number of classes
#define D 256            // feature dim
#define NCONS 8          // consumer warps (4 dim-slices x 2 row-groups)
#define PROD_W 8         // producer warp id
#define TROWS 12         // rows per bulk tile
#define BLK 288          // 9 warps
#define NBLOCKS 148      // one block per SM

// dynamic smem layout (bytes)
#define SOFF_ACC   0                         // 8 copies x 100 x 64 fl = 204800
#define SOFF_FEAT  204800                    // 2 stages x 12 rows x 1024 = 24576
#define SOFF_LAB   (SOFF_FEAT + 2*TROWS*1024)        // 2 x 12 x 4 = 96
#define SOFF_MBAR  (SOFF_LAB + 96)                   // full0,full1,empty0,empty1 = 32
#define SOFF_HIST  (SOFF_MBAR + 32)                  // 400
#define SMEM_TOTAL (SOFF_HIST + 400)                 // 229,928 < 232,448 opt-in max

__device__ float g_sums[C * D];
__device__ float g_counts[C];
__device__ int   g_label_is_i64;   // 1 => labels are int64 (stride-2 int32 words)

// ---------------------------------------------------------------------------
__global__ void k_seed() { g_label_is_i64 = 1; }

__global__ void k_detect(const unsigned int* __restrict__ lw, int nwords) {
    int i = blockIdx.x * blockDim.x + threadIdx.x;
    if (i < C * D) g_sums[i] = 0.0f;
    if (i < C)     g_counts[i] = 0.0f;
    int idx = 2 * i + 1;   // odd words zero <=> little-endian int64 labels
    if (idx < nwords && lw[idx] != 0u) g_label_is_i64 = 0;
}

__device__ __forceinline__ int load_label(const int* __restrict__ l32, int i, int is64) {
    return __ldg(&l32[is64 ? (i << 1) : i]);
}

// ---- mbarrier / bulk-async primitives --------------------------------------
__device__ __forceinline__ unsigned smem_u32(const void* p) {
    return (unsigned)__cvta_generic_to_shared(p);
}
__device__ __forceinline__ void mbar_init(unsigned a, unsigned cnt) {
    asm volatile("mbarrier.init.shared.b64 [%0], %1;" :: "r"(a), "r"(cnt) : "memory");
}
__device__ __forceinline__ void mbar_expect_tx(unsigned a, unsigned bytes) {
    asm volatile("mbarrier.arrive.expect_tx.shared.b64 _, [%0], %1;"
                 :: "r"(a), "r"(bytes) : "memory");
}
__device__ __forceinline__ void mbar_arrive(unsigned a) {
    asm volatile("mbarrier.arrive.shared.b64 _, [%0];" :: "r"(a) : "memory");
}
__device__ __forceinline__ void mbar_wait(unsigned a, int parity) {
    asm volatile(
        "{\n\t.reg .pred P;\n\t"
        "W_%=:\n\t"
        "mbarrier.try_wait.parity.acquire.cta.shared::cta.b64 P, [%0], %1, 0x989680;\n\t"
        "@P bra.uni DN_%=;\n\t"
        "bra.uni W_%=;\n\t"
        "DN_%=:\n\t}"
        :: "r"(a), "r"(parity) : "memory");
}
__device__ __forceinline__ void bulk_g2s(unsigned dst, const void* src,
                                         unsigned bytes, unsigned mbar) {
    asm volatile(
        "cp.async.bulk.shared::cta.global.mbarrier::complete_tx::bytes [%0], [%1], %2, [%3];"
        :: "r"(dst), "l"(src), "r"(bytes), "r"(mbar) : "memory");
}

// ---------------------------------------------------------------------------
// k_accum: producer/consumer segment-sum. 148 blocks (1/SM), 9 warps.
// Warp 8 streams feat via cp.async.bulk into double-buffered staging (bulk
// engine bypasses the SM's L1tex queue); warps 0-7 (slice s=w&3, rowgroup
// g=w>>2) run the smem RMW chains against private accumulators at clean LDS
// latency. Labels staged by the producer (STS + release-arrive ordering).
// ---------------------------------------------------------------------------
__global__ void __launch_bounds__(BLK)
k_accum(const float* __restrict__ feat, const int* __restrict__ l32,
        int N, int rows_per_block) {
    extern __shared__ char smem[];
    float* accf = (float*)(smem + SOFF_ACC);
    int*   histS = (int*)(smem + SOFF_HIST);
    const unsigned sbase = smem_u32(smem);
    const unsigned FULL0  = sbase + SOFF_MBAR;
    const unsigned EMPTY0 = sbase + SOFF_MBAR + 16;

    const int tid  = threadIdx.x;
    const int w    = tid >> 5;
    const int lane = tid & 31;

    for (int i = tid; i < NCONS * C * 64; i += BLK) accf[i] = 0.0f;
    for (int i = tid; i < C; i += BLK) histS[i] = 0;
    if (tid == 0) {
        mbar_init(FULL0,      1);  mbar_init(FULL0 + 8,  1);
        mbar_init(EMPTY0, NCONS);  mbar_init(EMPTY0 + 8, NCONS);
    }
    __syncthreads();

    const int is64 = g_label_is_i64;
    const int r0 = blockIdx.x * rows_per_block;
    const int r1 = min(r0 + rows_per_block, N);
    const int nrows = (r1 > r0) ? (r1 - r0) : 0;
    const int NT = nrows / TROWS;            // full tiles
    const int tail0 = r0 + NT * TROWS;

    if (w == PROD_W) {
        // ---------------- producer ----------------
        int pphase = 1;                       // first empty-waits pass
        for (int t = 0; t < NT; t++) {
            const int st = t & 1;
            mbar_wait(EMPTY0 + st * 8, pphase);
            if (st == 1) pphase ^= 1;
            const int gr0 = r0 + t * TROWS;
            if (lane < TROWS) {
                const int lab = load_label(l32, gr0 + lane, is64);
                *(int*)(smem + SOFF_LAB + st * (TROWS * 4) + lane * 4) = lab;
                atomicAdd(&histS[lab], 1);
            }
            __syncwarp();                     // STS done before release-arrive
            if (lane == 0) {
                mbar_expect_tx(FULL0 + st * 8, TROWS * 1024);
                bulk_g2s(sbase + SOFF_FEAT + st * (TROWS * 1024),
                         (const char*)feat + (size_t)gr0 * 1024,
                         TROWS * 1024, FULL0 + st * 8);
            }
        }
        // tail histogram
        for (int r = tail0 + lane; r < r1; r += 32)
            atomicAdd(&histS[load_label(l32, r, is64)], 1);
    } else {
        // ---------------- consumers ----------------
        const int s = w & 3;                  // dim slice (64 dims)
        const int g = w >> 2;                 // row parity group
        float2* __restrict__ acc2 = (float2*)(smem + SOFF_ACC + w * (C * 64 * 4));
        const int ROWS_PER = TROWS / 2;       // 6

        int cphase = 0;
        for (int t = 0; t < NT; t++) {
            const int st = t & 1;
            mbar_wait(FULL0 + st * 8, cphase);
            if (st == 1) cphase ^= 1;

            const char* fst = smem + SOFF_FEAT + st * (TROWS * 1024) + s * 256 + (lane << 3);
            const char* lst = smem + SOFF_LAB + st * (TROWS * 4);

            int    lab[ROWS_PER];
            float2 v[ROWS_PER];
            #pragma unroll
            for (int j = 0; j < ROWS_PER; j++) {
                const int r = g + 2 * j;
                lab[j] = *(const int*)(lst + r * 4);
                v[j]   = *(const float2*)(fst + r * 1024);
            }
            #pragma unroll
            for (int j = 0; j < ROWS_PER; j++) {
                const int a = lab[j] * 32 + lane;
                float2 tv = acc2[a];
                tv.x += v[j].x; tv.y += v[j].y;
                acc2[a] = tv;
            }
            __syncwarp();                     // all lanes done with stage
            if (lane == 0) mbar_arrive(EMPTY0 + st * 8);
        }
        // tail rows via direct LDG (few)
        for (int r = tail0 + g; r < r1; r += 2) {
            const int labr = load_label(l32, r, is64);
            const float2 vv = __ldg((const float2*)feat + (size_t)r * 128 + s * 32 + lane);
            const int a = labr * 32 + lane;
            float2 tv = acc2[a];
            tv.x += vv.x; tv.y += vv.y;
            acc2[a] = tv;
        }
    }
    __syncthreads();

    // reduce the 2 row-group copies per slice, flush to global
    for (int i = tid; i < 4 * C * 64; i += BLK) {
        const int slice = i / (C * 64);
        const int rem   = i - slice * (C * 64);      // c*64 + d
        const float val = accf[slice * (C * 64) + rem] +
                          accf[(slice + 4) * (C * 64) + rem];
        const int c = rem >> 6;
        const int d = rem & 63;
        atomicAdd(&g_sums[c * D + slice * 64 + d], val);
    }
    for (int i = tid; i < C; i += BLK)
        if (histS[i]) atomicAdd(&g_counts[i], (float)histS[i]);
}

// ---------------------------------------------------------------------------
// k_dist: per-row distance to own-class center (sums*inv_cnt on the fly).
// Two rows per warp, loads front-batched.
// ---------------------------------------------------------------------------
__global__ void __launch_bounds__(256)
k_dist(const float* __restrict__ feat, const int* __restrict__ l32,
       float* __restrict__ out, int N) {
    const int gw   = (int)((blockIdx.x * blockDim.x + threadIdx.x) >> 5);
    const int lane = threadIdx.x & 31;
    const int row0 = 2 * gw;
    const int row1 = row0 + 1;
    if (row0 >= N) return;
    const bool has1 = (row1 < N);

    const int is64 = g_label_is_i64;
    const int lab0 = load_label(l32, row0, is64);
    const int lab1 = has1 ? load_label(l32, row1, is64) : lab0;

    const float4* __restrict__ f0 = (const float4*)(feat + (size_t)row0 * D);
    const float4* __restrict__ f1 = (const float4*)(feat + (size_t)row1 * D);
    const float4* __restrict__ s0 = (const float4*)(g_sums + (size_t)lab0 * D);
    const float4* __restrict__ s1 = (const float4*)(g_sums + (size_t)lab1 * D);

    const float4 fa0 = __ldcs(&f0[lane]);
    const float4 fb0 = __ldcs(&f0[lane + 32]);
    const float4 fa1 = has1 ? __ldcs(&f1[lane])      : make_float4(0,0,0,0);
    const float4 fb1 = has1 ? __ldcs(&f1[lane + 32]) : make_float4(0,0,0,0);
    const float4 sa0 = __ldg(&s0[lane]);
    const float4 sb0 = __ldg(&s0[lane + 32]);
    const float4 sa1 = __ldg(&s1[lane]);
    const float4 sb1 = __ldg(&s1[lane + 32]);

    const float c0 = __ldg(&g_counts[lab0]);
    const float c1 = __ldg(&g_counts[lab1]);
    const float inv0 = (c0 > 0.0f) ? (1.0f / c0) : 0.0f;
    const float inv1 = (c1 > 0.0f) ? (1.0f / c1) : 0.0f;

    float d0 = 0.0f, d1 = 0.0f, dx;
    dx = fa0.x - sa0.x * inv0; d0 = fmaf(dx, dx, d0);
    dx = fa0.y - sa0.y * inv0; d0 = fmaf(dx, dx, d0);
    dx = fa0.z - sa0.z * inv0; d0 = fmaf(dx, dx, d0);
    dx = fa0.w - sa0.w * inv0; d0 = fmaf(dx, dx, d0);
    dx = fb0.x - sb0.x * inv0; d0 = fmaf(dx, dx, d0);
    dx = fb0.y - sb0.y * inv0; d0 = fmaf(dx, dx, d0);
    dx = fb0.z - sb0.z * inv0; d0 = fmaf(dx, dx, d0);
    dx = fb0.w - sb0.w * inv0; d0 = fmaf(dx, dx, d0);

    dx = fa1.x - sa1.x * inv1; d1 = fmaf(dx, dx, d1);
    dx = fa1.y - sa1.y * inv1; d1 = fmaf(dx, dx, d1);
    dx = fa1.z - sa1.z * inv1; d1 = fmaf(dx, dx, d1);
    dx = fa1.w - sa1.w * inv1; d1 = fmaf(dx, dx, d1);
    dx = fb1.x - sb1.x * inv1; d1 = fmaf(dx, dx, d1);
    dx = fb1.y - sb1.y * inv1; d1 = fmaf(dx, dx, d1);
    dx = fb1.z - sb1.z * inv1; d1 = fmaf(dx, dx, d1);
    dx = fb1.w - sb1.w * inv1; d1 = fmaf(dx, dx, d1);

    #pragma unroll
    for (int o = 16; o; o >>= 1) {
        d0 += __shfl_xor_sync(0xffffffffu, d0, o);
        d1 += __shfl_xor_sync(0xffffffffu, d1, o);
    }
    if (lane == 0) {
        out[row0] = sqrtf(d0);
        if (has1) out[row1] = sqrtf(d1);
    }
}

// ---------------------------------------------------------------------------
extern "C" void kernel_launch(void* const* d_in, const int* in_sizes, int n_in,
                              void* d_out, int out_size) {
    const float* feat = (const float*)d_in[0];
    const int*   l32  = (const int*)d_in[1];
    float* out = (float*)d_out;

    const int N = in_sizes[0] / D;             // 500000

    static int attr_done = 0;
    if (!attr_done) {
        cudaFuncSetAttribute(k_accum, cudaFuncAttributeMaxDynamicSharedMemorySize,
                             SMEM_TOTAL);
        attr_done = 1;
    }

    k_seed<<<1, 32>>>();
    {
        int work = (N / 2 > C * D) ? N / 2 : C * D;
        k_detect<<<(work + 255) / 256, 256>>>((const unsigned int*)l32, N);
    }
    {
        int rpb = (N + NBLOCKS - 1) / NBLOCKS;  // 3379
        k_accum<<<NBLOCKS, BLK, SMEM_TOTAL>>>(feat, l32, N, rpb);
    }
    {
        int blocks = (N + 15) / 16;             // 8 warps x 2 rows
        k_dist<<<blocks, 256>>>(feat, l32, out, N);
    }
}

// round 6
// speedup vs baseline: 1.1372x; 1.1372x over previous
#include <cuda_runtime.h>
#include <math.h>

#define C 100            // number of classes
#define D 256            // feature dim
#define SLICE 64         // dims per warp (float2 per lane)
#define NSLICES (D / SLICE)     // 4
#define ACC_WARPS 2      // warps per block; smem = 2*100*64*4 = 51.2KB
#define GY 148           // 4*148 = 592 blocks = one wave at 4 blocks/SM
#define BATCH 8          // rows per register batch (dedup group)

__device__ float g_sums[C * D];
__device__ float g_counts[C];
__device__ int   g_label_is_i64;   // 1 => labels are int64 (stride-2 int32 words)

// ---------------------------------------------------------------------------
__global__ void k_seed() { g_label_is_i64 = 1; }

// Zero scratch + detect label dtype (odd 32-bit words all zero <=> int64).
__global__ void k_detect(const unsigned int* __restrict__ lw, int nwords) {
    int i = blockIdx.x * blockDim.x + threadIdx.x;
    if (i < C * D) g_sums[i] = 0.0f;
    if (i < C)     g_counts[i] = 0.0f;
    int idx = 2 * i + 1;
    if (idx < nwords && lw[idx] != 0u) g_label_is_i64 = 0;
}

__device__ __forceinline__ int load_label(const int* __restrict__ l32, int i, int is64) {
    return __ldg(&l32[is64 ? (i << 1) : i]);
}

// ---------------------------------------------------------------------------
// k_accum: segment-sum with in-register label dedup to break the smem RMW
// scoreboard chain. Grid (NSLICES, GY), block 64 = 2 warps, private smem
// accumulator per warp (conflict-free float2 per lane). Depth-3 pipeline for
// DRAM MLP; per batch of 8 rows duplicates are merged in registers so the 8
// surviving RMWs issue as load-all / add-all / store-all (one scoreboard
// boundary per batch instead of 8 serial links).
// ---------------------------------------------------------------------------
__global__ void __launch_bounds__(ACC_WARPS * 32)
k_accum(const float2* __restrict__ feat2, const int* __restrict__ l32,
        int N, int rows_per_block) {
    __shared__ float acc[ACC_WARPS][C][SLICE];
    __shared__ int   hist[C];

    const int w    = threadIdx.x >> 5;
    const int lane = threadIdx.x & 31;
    const int dcol2 = blockIdx.x * (SLICE / 2) + lane;  // float2 column in row

    for (int i = threadIdx.x; i < ACC_WARPS * C * SLICE; i += blockDim.x)
        ((float*)acc)[i] = 0.0f;
    if (blockIdx.x == 0)
        for (int i = threadIdx.x; i < C; i += blockDim.x) hist[i] = 0;
    __syncthreads();

    const int is64 = g_label_is_i64;
    const int r0 = blockIdx.y * rows_per_block;
    const int r1 = min(r0 + rows_per_block, N);

    float2* __restrict__ accv = (float2*)&acc[w][0][0];   // [C*32] float2
    const int step = ACC_WARPS;
    const int first = r0 + w;
    const int cnt = (r1 > first) ? (r1 - first + step - 1) / step : 0;
    const int nb  = cnt / BATCH;
    const int bstride = BATCH * step;

    float2 vA[BATCH], vB[BATCH], vC[BATCH];
    int    lA[BATCH], lB[BATCH], lC[BATCH];

#define LOADB(V, L, BI)                                                       \
    {                                                                         \
        const int _rb = first + (BI) * bstride;                               \
        _Pragma("unroll")                                                     \
        for (int j = 0; j < BATCH; j++) {                                     \
            const int rr = _rb + j * step;                                    \
            (L)[j] = load_label(l32, rr, is64);                               \
            (V)[j] = __ldg(&feat2[(size_t)rr * (D / 2) + dcol2]);             \
        }                                                                     \
    }

// Dedup labels (branchless selects; labels are warp-uniform), then batched
// RMW: all LDS before all STS -> independent issue, one SB boundary/batch.
#define RMWB(V, L)                                                            \
    {                                                                         \
        _Pragma("unroll")                                                     \
        for (int j = 1; j < BATCH; j++) {                                     \
            _Pragma("unroll")                                                 \
            for (int i = 0; i < j; i++) {                                     \
                const bool dup = ((L)[i] == (L)[j]);                          \
                (V)[j].x += dup ? (V)[i].x : 0.0f;                            \
                (V)[j].y += dup ? (V)[i].y : 0.0f;                            \
                (L)[i] = dup ? -1 : (L)[i];                                   \
            }                                                                 \
        }                                                                     \
        float2 t[BATCH];                                                      \
        _Pragma("unroll")                                                     \
        for (int j = 0; j < BATCH; j++)                                       \
            if ((L)[j] >= 0) t[j] = accv[(L)[j] * 32 + lane];                 \
        _Pragma("unroll")                                                     \
        for (int j = 0; j < BATCH; j++) {                                     \
            t[j].x += (V)[j].x; t[j].y += (V)[j].y;                           \
        }                                                                     \
        _Pragma("unroll")                                                     \
        for (int j = 0; j < BATCH; j++)                                       \
            if ((L)[j] >= 0) accv[(L)[j] * 32 + lane] = t[j];                 \
    }

    if (nb >= 2) {
        LOADB(vA, lA, 0);
        LOADB(vB, lB, 1);
        int b = 0;
        for (; b + 5 <= nb; b += 3) {
            LOADB(vC, lC, b + 2); RMWB(vA, lA);
            LOADB(vA, lA, b + 3); RMWB(vB, lB);
            LOADB(vB, lB, b + 4); RMWB(vC, lC);
        }
        const int rem = nb - b;            // 2, 3, or 4
        if (rem == 2) {
            RMWB(vA, lA); RMWB(vB, lB);
        } else if (rem == 3) {
            LOADB(vC, lC, b + 2); RMWB(vA, lA);
            RMWB(vB, lB); RMWB(vC, lC);
        } else {                            // rem == 4
            LOADB(vC, lC, b + 2); RMWB(vA, lA);
            LOADB(vA, lA, b + 3); RMWB(vB, lB);
            RMWB(vC, lC); RMWB(vA, lA);
        }
    } else if (nb == 1) {
        LOADB(vA, lA, 0);
        RMWB(vA, lA);
    }
    // tail rows (serial RMW, few)
    for (int rr = first + nb * bstride; rr < r1; rr += step) {
        const int la = load_label(l32, rr, is64);
        const float2 v = __ldg(&feat2[(size_t)rr * (D / 2) + dcol2]);
        const int a = la * (SLICE / 2) + lane;
        float2 t = accv[a];
        t.x += v.x; t.y += v.y;
        accv[a] = t;
    }

#undef LOADB
#undef RMWB

    if (blockIdx.x == 0) {
        for (int i = r0 + threadIdx.x; i < r1; i += blockDim.x)
            atomicAdd(&hist[load_label(l32, i, is64)], 1);
    }
    __syncthreads();

    // reduce warp copies, flush with atomics
    const int dbase = blockIdx.x * SLICE;
    for (int i = threadIdx.x; i < C * SLICE; i += blockDim.x) {
        float s = 0.0f;
        #pragma unroll
        for (int ww = 0; ww < ACC_WARPS; ww++) s += (&acc[ww][0][0])[i];
        const int cls = i / SLICE;
        const int dd  = i - cls * SLICE;
        atomicAdd(&g_sums[cls * D + dbase + dd], s);
    }
    if (blockIdx.x == 0) {
        for (int i = threadIdx.x; i < C; i += blockDim.x)
            if (hist[i]) atomicAdd(&g_counts[i], (float)hist[i]);
    }
}

// ---------------------------------------------------------------------------
// k_dist: per-row distance to own-class center (sums*inv_cnt on the fly).
// Two rows per warp, loads front-batched. (R4 version, 93 µs / 70% DRAM.)
// ---------------------------------------------------------------------------
__global__ void __launch_bounds__(256)
k_dist(const float* __restrict__ feat, const int* __restrict__ l32,
       float* __restrict__ out, int N) {
    const int gw   = (int)((blockIdx.x * blockDim.x + threadIdx.x) >> 5);
    const int lane = threadIdx.x & 31;
    const int row0 = 2 * gw;
    const int row1 = row0 + 1;
    if (row0 >= N) return;
    const bool has1 = (row1 < N);

    const int is64 = g_label_is_i64;
    const int lab0 = load_label(l32, row0, is64);
    const int lab1 = has1 ? load_label(l32, row1, is64) : lab0;

    const float4* __restrict__ f0 = (const float4*)(feat + (size_t)row0 * D);
    const float4* __restrict__ f1 = (const float4*)(feat + (size_t)row1 * D);
    const float4* __restrict__ s0 = (const float4*)(g_sums + (size_t)lab0 * D);
    const float4* __restrict__ s1 = (const float4*)(g_sums + (size_t)lab1 * D);

    const float4 fa0 = __ldcs(&f0[lane]);
    const float4 fb0 = __ldcs(&f0[lane + 32]);
    const float4 fa1 = has1 ? __ldcs(&f1[lane])      : make_float4(0,0,0,0);
    const float4 fb1 = has1 ? __ldcs(&f1[lane + 32]) : make_float4(0,0,0,0);
    const float4 sa0 = __ldg(&s0[lane]);
    const float4 sb0 = __ldg(&s0[lane + 32]);
    const float4 sa1 = __ldg(&s1[lane]);
    const float4 sb1 = __ldg(&s1[lane + 32]);

    const float c0 = __ldg(&g_counts[lab0]);
    const float c1 = __ldg(&g_counts[lab1]);
    const float inv0 = (c0 > 0.0f) ? (1.0f / c0) : 0.0f;
    const float inv1 = (c1 > 0.0f) ? (1.0f / c1) : 0.0f;

    float d0 = 0.0f, d1 = 0.0f, dx;
    dx = fa0.x - sa0.x * inv0; d0 = fmaf(dx, dx, d0);
    dx = fa0.y - sa0.y * inv0; d0 = fmaf(dx, dx, d0);
    dx = fa0.z - sa0.z * inv0; d0 = fmaf(dx, dx, d0);
    dx = fa0.w - sa0.w * inv0; d0 = fmaf(dx, dx, d0);
    dx = fb0.x - sb0.x * inv0; d0 = fmaf(dx, dx, d0);
    dx = fb0.y - sb0.y * inv0; d0 = fmaf(dx, dx, d0);
    dx = fb0.z - sb0.z * inv0; d0 = fmaf(dx, dx, d0);
    dx = fb0.w - sb0.w * inv0; d0 = fmaf(dx, dx, d0);

    dx = fa1.x - sa1.x * inv1; d1 = fmaf(dx, dx, d1);
    dx = fa1.y - sa1.y * inv1; d1 = fmaf(dx, dx, d1);
    dx = fa1.z - sa1.z * inv1; d1 = fmaf(dx, dx, d1);
    dx = fa1.w - sa1.w * inv1; d1 = fmaf(dx, dx, d1);
    dx = fb1.x - sb1.x * inv1; d1 = fmaf(dx, dx, d1);
    dx = fb1.y - sb1.y * inv1; d1 = fmaf(dx, dx, d1);
    dx = fb1.z - sb1.z * inv1; d1 = fmaf(dx, dx, d1);
    dx = fb1.w - sb1.w * inv1; d1 = fmaf(dx, dx, d1);

    #pragma unroll
    for (int o = 16; o; o >>= 1) {
        d0 += __shfl_xor_sync(0xffffffffu, d0, o);
        d1 += __shfl_xor_sync(0xffffffffu, d1, o);
    }
    if (lane == 0) {
        out[row0] = sqrtf(d0);
        if (has1) out[row1] = sqrtf(d1);
    }
}

// ---------------------------------------------------------------------------
extern "C" void kernel_launch(void* const* d_in, const int* in_sizes, int n_in,
                              void* d_out, int out_size) {
    const float* feat = (const float*)d_in[0];
    const int*   l32  = (const int*)d_in[1];
    float* out = (float*)d_out;

    const int N = in_sizes[0] / D;             // 500000

    k_seed<<<1, 32>>>();
    {
        int work = (N / 2 > C * D) ? N / 2 : C * D;
        k_detect<<<(work + 255) / 256, 256>>>((const unsigned int*)l32, N);
    }
    {
        int rpb = (N + GY - 1) / GY;
        dim3 grid(NSLICES, GY);
        k_accum<<<grid, ACC_WARPS * 32>>>((const float2*)feat, l32, N, rpb);
    }
    {
        int blocks = (N + 15) / 16;             // 8 warps x 2 rows per warp
        k_dist<<<blocks, 256>>>(feat, l32, out, N);
    }
}

// round 8
// speedup vs baseline: 1.4128x; 1.2424x over previous
#include <cuda_runtime.h>
#include <math.h>

#define C 100            // number of classes
#define D 256            // feature dim
#define PCAP (1 << 20)   // capacity of the sorted-index scratch (N = 500000)
#define PB_CHUNK 144     // sorted rows per warp in the sum pass
#define DIST_ROWS 4      // rows per warp in the distance pass

__device__ float g_sums[C * D];
__device__ float g_counts[C];      // float counts for the distance pass
__device__ int   g_counti[C];      // int histogram
__device__ int   g_start[C];       // class start offsets (exclusive scan)
__device__ int   g_cursor[C];      // scatter cursors
__device__ int   g_packed[PCAP];   // (label << 24) | row, sorted by label
__device__ int   g_label_is_i64;   // 1 => labels are int64 (stride-2 int32 words)

// ---------------------------------------------------------------------------
__global__ void k_seed() { g_label_is_i64 = 1; }

// Zero scratch + detect label dtype (odd 32-bit words all zero <=> int64).
__global__ void k_detect(const unsigned int* __restrict__ lw, int nwords) {
    int i = blockIdx.x * blockDim.x + threadIdx.x;
    if (i < C * D) g_sums[i] = 0.0f;
    if (i < C)     g_counti[i] = 0;
    int idx = 2 * i + 1;
    if (idx < nwords && lw[idx] != 0u) g_label_is_i64 = 0;
}

__device__ __forceinline__ int load_label(const int* __restrict__ l32, int i, int is64) {
    return __ldg(&l32[is64 ? (i << 1) : i]);
}

// ---------------------------------------------------------------------------
// Pass A1: label histogram (block-local smem, one flush per block).
// ---------------------------------------------------------------------------
__global__ void k_hist(const int* __restrict__ l32, int N, int rows_per_block) {
    __shared__ int h[C];
    for (int i = threadIdx.x; i < C; i += blockDim.x) h[i] = 0;
    __syncthreads();
    const int is64 = g_label_is_i64;
    const int r0 = blockIdx.x * rows_per_block;
    const int r1 = min(r0 + rows_per_block, N);
    for (int i = r0 + threadIdx.x; i < r1; i += blockDim.x)
        atomicAdd(&h[load_label(l32, i, is64)], 1);
    __syncthreads();
    for (int i = threadIdx.x; i < C; i += blockDim.x)
        if (h[i]) atomicAdd(&g_counti[i], h[i]);
}

// ---------------------------------------------------------------------------
// Pass A2: exclusive scan of the 100 counts (single block).
// ---------------------------------------------------------------------------
__global__ void k_scan() {
    __shared__ int sc[128];
    const int c = threadIdx.x;
    const int v = (c < C) ? g_counti[c] : 0;
    sc[c] = v;
    __syncthreads();
    #pragma unroll
    for (int off = 1; off < 128; off <<= 1) {
        int t = (c >= off) ? sc[c - off] : 0;
        __syncthreads();
        sc[c] += t;
        __syncthreads();
    }
    if (c < C) {
        const int ex = sc[c] - v;
        g_start[c]  = ex;
        g_cursor[c] = ex;
        g_counts[c] = (float)v;
    }
}

// ---------------------------------------------------------------------------
// Pass A3: scatter (label<<24 | row) into class-sorted order. Block-local
// histogram to reserve a per-class range with ONE global atomic per class.
// Within-block order is nondeterministic but the SET per class is exact and
// fp sums over a permuted set still verify well within 1e-3.
// ---------------------------------------------------------------------------
__global__ void k_scatter(const int* __restrict__ l32, int N, int rows_per_block) {
    __shared__ int h[C];
    __shared__ int base[C];
    for (int i = threadIdx.x; i < C; i += blockDim.x) h[i] = 0;
    __syncthreads();
    const int is64 = g_label_is_i64;
    const int r0 = blockIdx.x * rows_per_block;
    const int r1 = min(r0 + rows_per_block, N);
    for (int i = r0 + threadIdx.x; i < r1; i += blockDim.x)
        atomicAdd(&h[load_label(l32, i, is64)], 1);
    __syncthreads();
    for (int i = threadIdx.x; i < C; i += blockDim.x) {
        base[i] = atomicAdd(&g_cursor[i], h[i]);
        h[i] = 0;
    }
    __syncthreads();
    for (int i = r0 + threadIdx.x; i < r1; i += blockDim.x) {
        const int lab = load_label(l32, i, is64);
        const int loc = atomicAdd(&h[lab], 1);
        g_packed[base[lab] + loc] = (lab << 24) | i;
    }
}

// ---------------------------------------------------------------------------
// Pass B: segment-sum over class-sorted rows. One warp per PB_CHUNK sorted
// positions; each lane accumulates 8 dims (2 x float4) in REGISTERS — no
// smem RMW at all. Flush to g_sums only at class changes (~1 per warp).
// Depth-2 pipeline of 4-row batches keeps 8 LDG.128 in flight per warp.
// ---------------------------------------------------------------------------
__global__ void __launch_bounds__(256)
k_sum_sorted(const float* __restrict__ feat, int total) {
    const int gw   = (int)((blockIdx.x * blockDim.x + threadIdx.x) >> 5);
    const int lane = threadIdx.x & 31;
    const int p0 = gw * PB_CHUNK;
    const int p1 = min(p0 + PB_CHUNK, total);
    if (p0 >= p1) return;

    float4 a0 = make_float4(0, 0, 0, 0);
    float4 a1 = make_float4(0, 0, 0, 0);
    int cur = __ldg(&g_packed[p0]) >> 24;

#define FLUSH()                                                               \
    do {                                                                      \
        float* dp = &g_sums[cur * D + (lane << 2)];                           \
        atomicAdd(dp + 0, a0.x); atomicAdd(dp + 1, a0.y);                     \
        atomicAdd(dp + 2, a0.z); atomicAdd(dp + 3, a0.w);                     \
        atomicAdd(dp + 128, a1.x); atomicAdd(dp + 129, a1.y);                 \
        atomicAdd(dp + 130, a1.z); atomicAdd(dp + 131, a1.w);                 \
        a0.x = a0.y = a0.z = a0.w = 0.0f;                                     \
        a1.x = a1.y = a1.z = a1.w = 0.0f;                                     \
    } while (0)

    int pkA[4], pkB[4];
    float4 vaA[4], vbA[4], vaB[4], vbB[4];

#define PLOAD(PK, VA, VB, P, M)                                               \
    do {                                                                      \
        _Pragma("unroll")                                                     \
        for (int j = 0; j < 4; j++) if (j < (M)) {                            \
            (PK)[j] = __ldg(&g_packed[(P) + j]);                              \
            const float4* f4 =                                                \
                (const float4*)(feat + (size_t)((PK)[j] & 0xFFFFFF) * D);     \
            (VA)[j] = __ldcs(&f4[lane]);                                      \
            (VB)[j] = __ldcs(&f4[lane + 32]);                                 \
        }                                                                     \
    } while (0)

#define PPROC(PK, VA, VB, M)                                                  \
    do {                                                                      \
        _Pragma("unroll")                                                     \
        for (int j = 0; j < 4; j++) if (j < (M)) {                            \
            const int lab = (PK)[j] >> 24;                                    \
            if (lab != cur) { FLUSH(); cur = lab; }                           \
            a0.x += (VA)[j].x; a0.y += (VA)[j].y;                             \
            a0.z += (VA)[j].z; a0.w += (VA)[j].w;                             \
            a1.x += (VB)[j].x; a1.y += (VB)[j].y;                             \
            a1.z += (VB)[j].z; a1.w += (VB)[j].w;                             \
        }                                                                     \
    } while (0)

    int p = p0;
    int m = min(4, p1 - p);
    PLOAD(pkA, vaA, vbA, p, m);
    int pn = p + m;
    int useA = 1;
    while (pn < p1) {
        const int mn = min(4, p1 - pn);
        if (useA) {
            PLOAD(pkB, vaB, vbB, pn, mn);
            PPROC(pkA, vaA, vbA, m);
        } else {
            PLOAD(pkA, vaA, vbA, pn, mn);
            PPROC(pkB, vaB, vbB, m);
        }
        useA ^= 1;
        pn += mn;
        m = mn;
    }
    if (useA) {
        PPROC(pkA, vaA, vbA, m);
    } else {
        PPROC(pkB, vaB, vbB, m);
    }
    FLUSH();

#undef PLOAD
#undef PPROC
#undef FLUSH
}

// ---------------------------------------------------------------------------
// k_dist: per-row distance to own-class center (sums*inv_cnt on the fly).
// FOUR rows per warp; all 16 feat/sums loads front-batched for MLP.
// ---------------------------------------------------------------------------
__global__ void __launch_bounds__(256)
k_dist(const float* __restrict__ feat, const int* __restrict__ l32,
       float* __restrict__ out, int N) {
    const int gw   = (int)((blockIdx.x * blockDim.x + threadIdx.x) >> 5);
    const int lane = threadIdx.x & 31;
    const int row0 = DIST_ROWS * gw;
    if (row0 >= N) return;
    const int nr = min(DIST_ROWS, N - row0);

    const int is64 = g_label_is_i64;
    int lab[DIST_ROWS];
    #pragma unroll
    for (int j = 0; j < DIST_ROWS; j++)
        lab[j] = (j < nr) ? load_label(l32, row0 + j, is64) : 0;

    float4 fa[DIST_ROWS], fb[DIST_ROWS], sa[DIST_ROWS], sb[DIST_ROWS];
    #pragma unroll
    for (int j = 0; j < DIST_ROWS; j++) {
        const float4* f4 = (const float4*)(feat + (size_t)(row0 + j) * D);
        if (j < nr) {
            fa[j] = __ldcs(&f4[lane]);
            fb[j] = __ldcs(&f4[lane + 32]);
        } else {
            fa[j] = make_float4(0, 0, 0, 0);
            fb[j] = make_float4(0, 0, 0, 0);
        }
    }
    #pragma unroll
    for (int j = 0; j < DIST_ROWS; j++) {
        const float4* s4 = (const float4*)(g_sums + (size_t)lab[j] * D);
        sa[j] = __ldg(&s4[lane]);
        sb[j] = __ldg(&s4[lane + 32]);
    }

    float dsq[DIST_ROWS];
    #pragma unroll
    for (int j = 0; j < DIST_ROWS; j++) {
        const float cnt = __ldg(&g_counts[lab[j]]);
        const float inv = (cnt > 0.0f) ? (1.0f / cnt) : 0.0f;
        float s = 0.0f, dx;
        dx = fa[j].x - sa[j].x * inv; s = fmaf(dx, dx, s);
        dx = fa[j].y - sa[j].y * inv; s = fmaf(dx, dx, s);
        dx = fa[j].z - sa[j].z * inv; s = fmaf(dx, dx, s);
        dx = fa[j].w - sa[j].w * inv; s = fmaf(dx, dx, s);
        dx = fb[j].x - sb[j].x * inv; s = fmaf(dx, dx, s);
        dx = fb[j].y - sb[j].y * inv; s = fmaf(dx, dx, s);
        dx = fb[j].z - sb[j].z * inv; s = fmaf(dx, dx, s);
        dx = fb[j].w - sb[j].w * inv; s = fmaf(dx, dx, s);
        dsq[j] = s;
    }

    #pragma unroll
    for (int o = 16; o; o >>= 1) {
        #pragma unroll
        for (int j = 0; j < DIST_ROWS; j++)
            dsq[j] += __shfl_xor_sync(0xffffffffu, dsq[j], o);
    }
    if (lane == 0) {
        #pragma unroll
        for (int j = 0; j < DIST_ROWS; j++)
            if (j < nr) out[row0 + j] = sqrtf(dsq[j]);
    }
}

// ---------------------------------------------------------------------------
extern "C" void kernel_launch(void* const* d_in, const int* in_sizes, int n_in,
                              void* d_out, int out_size) {
    const float* feat = (const float*)d_in[0];
    const int*   l32  = (const int*)d_in[1];
    float* out = (float*)d_out;

    const int N = in_sizes[0] / D;             // 500000

    k_seed<<<1, 32>>>();
    {
        int work = (N / 2 > C * D) ? N / 2 : C * D;
        k_detect<<<(work + 255) / 256, 256>>>((const unsigned int*)l32, N);
    }
    {
        int nb = 128;
        int rpb = (N + nb - 1) / nb;
        k_hist<<<nb, 256>>>(l32, N, rpb);
    }
    k_scan<<<1, 128>>>();
    {
        int nb = 64;
        int rpb = (N + nb - 1) / nb;
        k_scatter<<<nb, 256>>>(l32, N, rpb);
    }
    {
        int rows_per_block = 8 * PB_CHUNK;      // 8 warps per block
        int blocks = (N + rows_per_block - 1) / rows_per_block;
        k_sum_sorted<<<blocks, 256>>>(feat, N);
    }
    {
        int rows_per_block = 8 * DIST_ROWS;     // 8 warps x 4 rows
        int blocks = (N + rows_per_block - 1) / rows_per_block;
        k_dist<<<blocks, 256>>>(feat, l32, out, N);
    }
}